// round 5
// baseline (speedup 1.0000x reference)
#include <cuda_runtime.h>
#include <cuda_bf16.h>
#include <cstdint>

// NetVLAD fused warp-MMA kernel v3: warp-specialized loaders, double-buffered bf16
// tiles, fused finalize. x:[64,128,64,64] fp32 -> out:[64,8192] fp32.

#define NB      64
#define CC      128
#define KK      64
#define SS      4096
#define SPLITS  2
#define SPER    (SS / SPLITS)   // 2048
#define TP      128             // pixels per tile
#define NTILES  (SPER / TP)     // 16
#define THREADS 384             // 8 compute warps + 4 loader warps
#define CWARPS  8
#define CTHREADS 256

// SMEM layout (bytes)
#define OFF_XB   0               // x bf16 [128 p][256 B] swizzled, x2 buffers
#define OFF_W    65536           // w bf16 [64 k][256 B] swizzled
#define OFF_A    81920           // a bf16 [128 p][128 B] swizzled, x2 buffers
#define OFF_ASUM 114688          // 64 floats
#define SMEM_BYTES (OFF_ASUM + 256)

__device__ float g_vlad_part[SPLITS * NB * KK * CC];   // [split][n][k][c]
__device__ float g_asum_part[SPLITS * NB * KK];
__device__ unsigned int g_flag[NB];

__device__ __forceinline__ uint32_t smem_u32(const void* p) {
    uint32_t a;
    asm("{ .reg .u64 t; cvta.to.shared.u64 t, %1; cvt.u32.u64 %0, t; }" : "=r"(a) : "l"(p));
    return a;
}
__device__ __forceinline__ uint32_t swz256(int row, int byte) {
    return (uint32_t)(row * 256 + (byte ^ ((row & 7) << 4)));
}
__device__ __forceinline__ uint32_t swz128(int row, int byte) {
    return (uint32_t)(row * 128 + (byte ^ ((row & 7) << 4)));
}

#define BAR_SYNC(id, cnt) \
    asm volatile("bar.sync %0, %1;" :: "r"(id), "r"(cnt) : "memory")
#define BAR_ARRIVE(id, cnt) \
    asm volatile("bar.arrive %0, %1;" :: "r"(id), "r"(cnt) : "memory")

#define LDSM_X4(R, addr) \
    asm volatile("ldmatrix.sync.aligned.m8n8.x4.shared.b16 {%0,%1,%2,%3}, [%4];" \
        : "=r"((R)[0]), "=r"((R)[1]), "=r"((R)[2]), "=r"((R)[3]) : "r"(addr))
#define LDSM_X4T(R, addr) \
    asm volatile("ldmatrix.sync.aligned.m8n8.x4.trans.shared.b16 {%0,%1,%2,%3}, [%4];" \
        : "=r"((R)[0]), "=r"((R)[1]), "=r"((R)[2]), "=r"((R)[3]) : "r"(addr))

__device__ __forceinline__ void mma16816(float* d, const uint32_t* a,
                                         uint32_t b0, uint32_t b1) {
    asm volatile(
        "mma.sync.aligned.m16n8k16.row.col.f32.bf16.bf16.f32 "
        "{%0,%1,%2,%3}, {%4,%5,%6,%7}, {%8,%9}, {%0,%1,%2,%3};"
        : "+f"(d[0]), "+f"(d[1]), "+f"(d[2]), "+f"(d[3])
        : "r"(a[0]), "r"(a[1]), "r"(a[2]), "r"(a[3]), "r"(b0), "r"(b1));
}

// result = { lo = bf16(lo_f), hi = bf16(hi_f) }
__device__ __forceinline__ uint32_t pack_bf16x2(float lo_f, float hi_f) {
    uint32_t r;
    asm("cvt.rn.bf16x2.f32 %0, %1, %2;" : "=r"(r) : "f"(hi_f), "f"(lo_f));
    return r;
}

__global__ void __launch_bounds__(THREADS)
netvlad_mma(const float* __restrict__ x, const float* __restrict__ conv_w,
            const float* __restrict__ centroids, float* __restrict__ out) {
    extern __shared__ char smem[];
    const uint32_t sb = smem_u32(smem);
    const int tid  = threadIdx.x;
    const int lane = tid & 31;
    const int warp = tid >> 5;
    const int split = blockIdx.x;
    const int n     = blockIdx.y;

    if (tid < KK) ((float*)(smem + OFF_ASUM))[tid] = 0.f;

    // conv_w [64][128] -> bf16, swizzled rows (all threads)
    for (int i = tid; i < KK * CC; i += THREADS) {
        int k = i >> 7, c = i & 127;
        *(uint16_t*)(smem + OFF_W + swz256(k, c * 2)) =
            __bfloat16_as_ushort(__float2bfloat16_rn(conv_w[i]));
    }
    __syncthreads();

    const float* xb_g = x + ((size_t)n * CC) * SS + (size_t)split * SPER;

    if (warp >= CWARPS) {
        // ================= loader warps (4) =================
        const int lw = warp - CWARPS;          // 0..3
        const int p  = lw * 32 + lane;         // this warp's fixed pixel lane-row
        for (int t = 0; t < NTILES; ++t) {
            if (t >= 2) BAR_SYNC(2 + (t & 1), THREADS);       // wait buffer free
            const uint32_t xboff = OFF_XB + (uint32_t)(t & 1) * 32768;
            const float* xg = xb_g + (size_t)t * TP + p;
            #pragma unroll 8
            for (int pair = 0; pair < 64; ++pair) {
                const int c0 = pair * 2;
                float v0 = xg[(size_t)c0 * SS];
                float v1 = xg[(size_t)(c0 + 1) * SS];
                *(uint32_t*)(smem + xboff + swz256(p, c0 * 2)) = pack_bf16x2(v0, v1);
            }
            BAR_ARRIVE(t & 1, THREADS);                        // buffer full
        }
    } else {
        // ================= compute warps (8) =================
        float vacc[32];
        #pragma unroll
        for (int i = 0; i < 32; i++) vacc[i] = 0.f;
        float asum[16];
        #pragma unroll
        for (int i = 0; i < 16; i++) asum[i] = 0.f;

        const int mt = warp & 3;   // GEMM2 m-tile (clusters)
        const int ch = warp >> 2;  // GEMM2 n-half (channels)
        const int wp = warp * 16;  // GEMM1 pixel base

        for (int t = 0; t < NTILES; ++t) {
            BAR_SYNC(t & 1, THREADS);                          // buffer full
            const uint32_t xboff = OFF_XB + (uint32_t)(t & 1) * 32768;
            const uint32_t aoff  = OFF_A  + (uint32_t)(t & 1) * 16384;

            // ---- GEMM1: logits[p][k] = x . w^T ----
            float lacc[32];
            #pragma unroll
            for (int i = 0; i < 32; i++) lacc[i] = 0.f;

            #pragma unroll
            for (int ks = 0; ks < 8; ++ks) {
                uint32_t ah[4];
                {
                    int arow = wp + (lane & 15);
                    int abyte = ks * 32 + (lane >> 4) * 16;
                    LDSM_X4(ah, sb + xboff + swz256(arow, abyte));
                }
                uint32_t bh[16];
                #pragma unroll
                for (int np = 0; np < 4; ++np) {
                    int brow = np * 16 + (lane & 7) + ((lane >> 4) & 1) * 8;
                    int bbyte = ks * 32 + ((lane >> 3) & 1) * 16;
                    LDSM_X4(bh + np * 4, sb + OFF_W + swz256(brow, bbyte));
                }
                #pragma unroll
                for (int nt = 0; nt < 8; ++nt) {
                    int bi = (nt >> 1) * 4 + (nt & 1) * 2;
                    mma16816(lacc + nt * 4, ah, bh[bi], bh[bi + 1]);
                }
            }

            // ---- softmax over K (quad shuffle) ----
            float m1 = -1e30f, m2 = -1e30f;
            #pragma unroll
            for (int nt = 0; nt < 8; ++nt) {
                m1 = fmaxf(m1, fmaxf(lacc[nt * 4 + 0], lacc[nt * 4 + 1]));
                m2 = fmaxf(m2, fmaxf(lacc[nt * 4 + 2], lacc[nt * 4 + 3]));
            }
            #pragma unroll
            for (int o = 1; o <= 2; o <<= 1) {
                m1 = fmaxf(m1, __shfl_xor_sync(0xFFFFFFFFu, m1, o));
                m2 = fmaxf(m2, __shfl_xor_sync(0xFFFFFFFFu, m2, o));
            }
            float s1 = 0.f, s2 = 0.f;
            #pragma unroll
            for (int nt = 0; nt < 8; ++nt) {
                float e0 = __expf(lacc[nt * 4 + 0] - m1);
                float e1 = __expf(lacc[nt * 4 + 1] - m1);
                float e2 = __expf(lacc[nt * 4 + 2] - m2);
                float e3 = __expf(lacc[nt * 4 + 3] - m2);
                lacc[nt * 4 + 0] = e0; lacc[nt * 4 + 1] = e1;
                lacc[nt * 4 + 2] = e2; lacc[nt * 4 + 3] = e3;
                s1 += e0 + e1; s2 += e2 + e3;
            }
            #pragma unroll
            for (int o = 1; o <= 2; o <<= 1) {
                s1 += __shfl_xor_sync(0xFFFFFFFFu, s1, o);
                s2 += __shfl_xor_sync(0xFFFFFFFFu, s2, o);
            }
            const float i1 = 1.f / s1, i2 = 1.f / s2;

            // ---- a -> SMEM bf16, accumulate asum ----
            {
                int p1 = wp + (lane >> 2), p2 = p1 + 8;
                #pragma unroll
                for (int nt = 0; nt < 8; ++nt) {
                    float a0 = lacc[nt * 4 + 0] * i1, a1 = lacc[nt * 4 + 1] * i1;
                    float a2 = lacc[nt * 4 + 2] * i2, a3 = lacc[nt * 4 + 3] * i2;
                    asum[nt * 2 + 0] += a0 + a2;
                    asum[nt * 2 + 1] += a1 + a3;
                    int kbyte = nt * 16 + (lane & 3) * 4;
                    *(uint32_t*)(smem + aoff + swz128(p1, kbyte)) = pack_bf16x2(a0, a1);
                    *(uint32_t*)(smem + aoff + swz128(p2, kbyte)) = pack_bf16x2(a2, a3);
                }
            }
            BAR_SYNC(4, CTHREADS);                             // a visible to compute warps

            // ---- GEMM2: vlad^T[k][c] += a^T . x ----
            #pragma unroll
            for (int ps = 0; ps < 8; ++ps) {
                uint32_t aah[4];
                {
                    int arow = ps * 16 + (lane & 7) + (lane >> 4) * 8;
                    int abyte = mt * 32 + ((lane >> 3) & 1) * 16;
                    LDSM_X4T(aah, sb + aoff + swz128(arow, abyte));
                }
                uint32_t bxh[16];
                #pragma unroll
                for (int np = 0; np < 4; ++np) {
                    int brow = ps * 16 + (lane & 7) + ((lane >> 3) & 1) * 8;
                    int bbyte = ch * 128 + np * 32 + (lane >> 4) * 16;
                    LDSM_X4T(bxh + np * 4, sb + xboff + swz256(brow, bbyte));
                }
                #pragma unroll
                for (int nt = 0; nt < 8; ++nt) {
                    int bi = (nt >> 1) * 4 + (nt & 1) * 2;
                    mma16816(vacc + nt * 4, aah, bxh[bi], bxh[bi + 1]);
                }
            }
            BAR_ARRIVE(2 + (t & 1), THREADS);                  // buffer free
        }

        // ---- write vlad partials [k][c] ----
        {
            float* dst = g_vlad_part + (size_t)(split * NB + n) * (KK * CC);
            int k1 = mt * 16 + (lane >> 2), k2 = k1 + 8;
            #pragma unroll
            for (int nt = 0; nt < 8; ++nt) {
                int c = ch * 64 + nt * 8 + (lane & 3) * 2;
                *(float2*)(dst + k1 * CC + c) = make_float2(vacc[nt * 4 + 0], vacc[nt * 4 + 1]);
                *(float2*)(dst + k2 * CC + c) = make_float2(vacc[nt * 4 + 2], vacc[nt * 4 + 3]);
            }
        }
        // ---- asum: warp reduce + smem atomic combine ----
        #pragma unroll
        for (int i = 0; i < 16; ++i) {
            float s = asum[i];
            s += __shfl_xor_sync(0xFFFFFFFFu, s, 4);
            s += __shfl_xor_sync(0xFFFFFFFFu, s, 8);
            s += __shfl_xor_sync(0xFFFFFFFFu, s, 16);
            asum[i] = s;
        }
        if (lane < 4) {
            float* as = (float*)(smem + OFF_ASUM);
            #pragma unroll
            for (int nt = 0; nt < 8; ++nt) {
                atomicAdd(as + nt * 8 + lane * 2 + 0, asum[nt * 2 + 0]);
                atomicAdd(as + nt * 8 + lane * 2 + 1, asum[nt * 2 + 1]);
            }
        }
    }

    __syncthreads();
    if (tid < KK)
        g_asum_part[(size_t)(split * NB + n) * KK + tid] = ((float*)(smem + OFF_ASUM))[tid];

    // ---- signal partials ready ----
    __threadfence();
    __syncthreads();
    if (tid == 0) atomicAdd(&g_flag[n], 1u);

    if (split != 0) return;

    // ================= fused finalize (split-0 CTA, all 384 threads) =================
    if (tid == 0) { while (atomicAdd(&g_flag[n], 0u) < 2u) { } }
    __syncthreads();
    __threadfence();

    float* v      = (float*)(smem);                 // 32 KB (over XB0)
    float* fasum  = (float*)(smem + OFF_W);
    float* rowinv = (float*)(smem + OFF_W + 256);
    float* wsum   = (float*)(smem + OFF_W + 512);

    if (tid < KK)
        fasum[tid] = g_asum_part[(size_t)n * KK + tid] +
                     g_asum_part[(size_t)(NB + n) * KK + tid];
    __syncthreads();

    const float* p0 = g_vlad_part + (size_t)n * (KK * CC);
    const float* p1 = g_vlad_part + (size_t)(NB + n) * (KK * CC);
    for (int idx = tid; idx < KK * CC; idx += THREADS) {
        int k = idx >> 7;
        v[idx] = p0[idx] + p1[idx] - fasum[k] * centroids[idx];
    }
    __syncthreads();

    for (int k = warp; k < KK; k += THREADS / 32) {
        const float* row = v + k * CC;
        float s = 0.f;
        #pragma unroll
        for (int c = lane; c < CC; c += 32) { float tv = row[c]; s += tv * tv; }
        #pragma unroll
        for (int o = 16; o; o >>= 1) s += __shfl_xor_sync(0xFFFFFFFFu, s, o);
        if (lane == 0) rowinv[k] = rsqrtf(s);
    }
    __syncthreads();

    float local = 0.f;
    for (int idx = tid; idx < KK * CC; idx += THREADS) {
        float tv = v[idx] * rowinv[idx >> 7];
        v[idx] = tv;
        local += tv * tv;
    }
    #pragma unroll
    for (int o = 16; o; o >>= 1) local += __shfl_xor_sync(0xFFFFFFFFu, local, o);
    if (lane == 0) wsum[warp] = local;
    __syncthreads();
    if (tid == 0) {
        float s = 0.f;
        #pragma unroll
        for (int w = 0; w < THREADS / 32; ++w) s += wsum[w];
        wsum[0] = rsqrtf(s);
    }
    __syncthreads();
    const float ginv = wsum[0];

    for (int idx = tid; idx < KK * CC; idx += THREADS)
        out[(size_t)n * (KK * CC) + idx] = v[idx] * ginv;

    __syncthreads();
    if (tid == 0) atomicExch(&g_flag[n], 0u);   // reset for next graph replay
}

extern "C" void kernel_launch(void* const* d_in, const int* in_sizes, int n_in,
                              void* d_out, int out_size) {
    const float* x         = (const float*)d_in[0];
    const float* conv_w    = (const float*)d_in[1];
    const float* centroids = (const float*)d_in[2];
    float* out = (float*)d_out;

    cudaFuncSetAttribute(netvlad_mma, cudaFuncAttributeMaxDynamicSharedMemorySize, SMEM_BYTES);
    netvlad_mma<<<dim3(SPLITS, NB), THREADS, SMEM_BYTES>>>(x, conv_w, centroids, out);
}